// round 2
// baseline (speedup 1.0000x reference)
#include <cuda_runtime.h>

#define CDIM 128
#define NMAX 50000
#define EMAX 640000

// ---------------- scratch (static device globals; no allocation) ----------------
__device__ __align__(16) float g_deg[NMAX];             // edge count per mid node
__device__ __align__(16) float g_s[NMAX * CDIM];        // scatter-sum of x_src per mid node
__device__ __align__(16) float g_KV[NMAX * 2 * CDIM];   // [m][0:128]=K, [m][128:256]=V
__device__ __align__(16) float g_Q[NMAX * CDIM];
__device__ __align__(16) float g_Wc[256 * 256];         // folded weights, input-major [i][j]
__device__ __align__(16) float g_WqT[CDIM * CDIM];      // q_w transposed, input-major
__device__ __align__(16) float g_bc0[256];              // {k_b, v_b}
__device__ __align__(16) float g_bc1[256];              // {k_w@(b1+b2), v_w@(b1+b2)} (scaled by deg)
__device__ __align__(16) float g_scores[EMAX];
__device__ __align__(16) float g_escore[EMAX];
__device__ unsigned g_maxbits;
__device__ float g_Z;
__device__ int g_idx64;   // 1 if edge indices are int64, 0 if int32

// adaptive index fetch: element e of a logical index array
__device__ __forceinline__ int ld_idx(const void* p, size_t e) {
    if (g_idx64) return (int)((const long long*)p)[e];
    return ((const int*)p)[e];
}

// order-preserving float<->uint for atomicMax over signed floats
__device__ __forceinline__ unsigned flipf(float f) {
    unsigned u = __float_as_uint(f);
    return (u & 0x80000000u) ? ~u : (u | 0x80000000u);
}
__device__ __forceinline__ float unflipf(unsigned u) {
    return __uint_as_float((u & 0x80000000u) ? (u ^ 0x80000000u) : ~u);
}

// ---------------- detect index dtype ----------------
// For little-endian int64 indices (all < 2^31), every odd 32-bit word is 0.
// For random int32 indices in [0, 50000), odd words are nonzero w.h.p.
__global__ void k_detect(const int* __restrict__ ei1w) {
    int allzero = 1;
    for (int i = 0; i < 512; i++) {
        if (ei1w[2 * i + 1] != 0) { allzero = 0; break; }
    }
    g_idx64 = allzero;
}

// ---------------- zero scratch + output ----------------
__global__ void k_zero(float* __restrict__ out, int n_out, int nmid) {
    int i = blockIdx.x * blockDim.x + threadIdx.x;
    int stride = gridDim.x * blockDim.x;
    for (int t = i; t < nmid * CDIM; t += stride) g_s[t] = 0.f;
    for (int t = i; t < nmid; t += stride) g_deg[t] = 0.f;
    for (int t = i; t < n_out; t += stride) out[t] = 0.f;
    if (i == 0) { g_maxbits = 0u; g_Z = 0.f; }
}

// ---------------- fold weights: Wc = [[kw*W1, vw*W1],[kw*W2, vw*W2]] input-major ----------------
__global__ void k_fold(const float* __restrict__ W1w, const float* __restrict__ W2w,
                       const float* __restrict__ W1b, const float* __restrict__ W2b,
                       const float* __restrict__ qw,
                       const float* __restrict__ kw, const float* __restrict__ vw,
                       const float* __restrict__ kb, const float* __restrict__ vb) {
    int idx = blockIdx.x * blockDim.x + threadIdx.x;
    if (idx < 65536) {
        int i = idx >> 8, j = idx & 255;
        const float* Wa = (j < 128) ? kw : vw;
        int jj = j & 127;
        const float* Wx = (i < 128) ? W1w : W2w;
        int ii = i & 127;
        float acc = 0.f;
        #pragma unroll 8
        for (int t = 0; t < 128; t++) acc += Wa[jj * 128 + t] * Wx[t * 128 + ii];
        g_Wc[i * 256 + j] = acc;
    } else if (idx < 65536 + 16384) {
        int t2 = idx - 65536;
        int i = t2 >> 7, j = t2 & 127;
        g_WqT[i * 128 + j] = qw[j * 128 + i];
    } else if (idx < 65536 + 16384 + 256) {
        int j = idx - (65536 + 16384);
        const float* Wa = (j < 128) ? kw : vw;
        int jj = j & 127;
        float acc = 0.f;
        for (int t = 0; t < 128; t++) acc += Wa[jj * 128 + t] * (W1b[t] + W2b[t]);
        g_bc1[j] = acc;
        g_bc0[j] = (j < 128) ? kb[jj] : vb[jj];
    }
}

// ---------------- edge pass 1: deg[mid]++, s[mid] += x_src[src] ----------------
__global__ void k_scatter1(const float* __restrict__ xsrc, const void* __restrict__ ei1, int E1) {
    int warp = (blockIdx.x * blockDim.x + threadIdx.x) >> 5;
    int lane = threadIdx.x & 31;
    if (warp >= E1) return;
    int src = ld_idx(ei1, warp);
    int mid = ld_idx(ei1, (size_t)E1 + warp);
    float4 v = *(const float4*)(xsrc + (size_t)src * CDIM + lane * 4);
    float* p = g_s + (size_t)mid * CDIM + lane * 4;
    atomicAdd(p + 0, v.x);
    atomicAdd(p + 1, v.y);
    atomicAdd(p + 2, v.z);
    atomicAdd(p + 3, v.w);
    if (lane == 0) atomicAdd(&g_deg[mid], 1.0f);
}

// ---------------- node GEMMs ----------------
// KVMODE=true : out[m][j] = sum_i X2[m][i]*Wc[i][j] + bc0[j] + deg[m]*bc1[j]
//               where X2 = [deg*x_mid | s], KDIM=256, NLD=256, out=g_KV
// KVMODE=false: out[m][j] = sum_i x_dst[m][i]*WqT[i][j] + q_b[j], KDIM=128, NLD=128, out=g_Q
template <bool KVMODE>
__global__ void __launch_bounds__(256) k_gemm(const float* __restrict__ X, const float* __restrict__ qb, int M) {
    const int KDIM = KVMODE ? 256 : 128;
    const int NLD  = KVMODE ? 256 : 128;
    float* out = KVMODE ? g_KV : g_Q;
    const float* W = KVMODE ? g_Wc : g_WqT;

    __shared__ __align__(16) float As[16][128];
    __shared__ __align__(16) float Bs[16][128];
    __shared__ __align__(16) float degS[128];
    __shared__ __align__(16) float b0s[128];
    __shared__ __align__(16) float b1s[128];

    int tid = threadIdx.x;
    int m0 = blockIdx.x * 128;
    int n0 = blockIdx.y * 128;

    if (tid < 128) {
        int m = m0 + tid;
        if (KVMODE) {
            degS[tid] = (m < M) ? g_deg[m] : 0.f;
            b0s[tid] = g_bc0[n0 + tid];
            b1s[tid] = g_bc1[n0 + tid];
        } else {
            b0s[tid] = qb[tid];
        }
    }
    __syncthreads();

    int ty = tid >> 4, tx = tid & 15;
    float acc[8][8];
    #pragma unroll
    for (int i = 0; i < 8; i++)
        #pragma unroll
        for (int j = 0; j < 8; j++) acc[i][j] = 0.f;

    for (int kt = 0; kt < KDIM / 16; kt++) {
        #pragma unroll
        for (int ld = 0; ld < 2; ld++) {
            int fid = tid + ld * 256;
            // A tile: 128 rows x 16 k
            int r = fid >> 2;
            int kp = (fid & 3) * 4;
            int kg = kt * 16 + kp;
            int m = m0 + r;
            float4 av = make_float4(0.f, 0.f, 0.f, 0.f);
            if (m < M) {
                if (!KVMODE || kg < 128) {
                    av = *(const float4*)(X + (size_t)m * 128 + kg);
                    if (KVMODE) {
                        float d = degS[r];
                        av.x *= d; av.y *= d; av.z *= d; av.w *= d;
                    }
                } else {
                    av = *(const float4*)(g_s + (size_t)m * 128 + (kg - 128));
                }
            }
            As[kp + 0][r] = av.x;
            As[kp + 1][r] = av.y;
            As[kp + 2][r] = av.z;
            As[kp + 3][r] = av.w;
            // B tile: 16 k x 128 cols
            int k = fid >> 5;
            int c4 = (fid & 31) * 4;
            *(float4*)&Bs[k][c4] = *(const float4*)(W + (size_t)(kt * 16 + k) * NLD + n0 + c4);
        }
        __syncthreads();
        #pragma unroll
        for (int kk = 0; kk < 16; kk++) {
            float a[8], b[8];
            *(float4*)(a)     = *(const float4*)&As[kk][ty * 8];
            *(float4*)(a + 4) = *(const float4*)&As[kk][ty * 8 + 4];
            *(float4*)(b)     = *(const float4*)&Bs[kk][tx * 8];
            *(float4*)(b + 4) = *(const float4*)&Bs[kk][tx * 8 + 4];
            #pragma unroll
            for (int i = 0; i < 8; i++)
                #pragma unroll
                for (int j = 0; j < 8; j++) acc[i][j] += a[i] * b[j];
        }
        __syncthreads();
    }

    #pragma unroll
    for (int i = 0; i < 8; i++) {
        int m = m0 + ty * 8 + i;
        if (m >= M) continue;
        float d = KVMODE ? degS[ty * 8 + i] : 0.f;
        #pragma unroll
        for (int j4 = 0; j4 < 8; j4 += 4) {
            int cb = tx * 8 + j4;
            float4 o;
            o.x = acc[i][j4 + 0] + b0s[cb + 0] + (KVMODE ? d * b1s[cb + 0] : 0.f);
            o.y = acc[i][j4 + 1] + b0s[cb + 1] + (KVMODE ? d * b1s[cb + 1] : 0.f);
            o.z = acc[i][j4 + 2] + b0s[cb + 2] + (KVMODE ? d * b1s[cb + 2] : 0.f);
            o.w = acc[i][j4 + 3] + b0s[cb + 3] + (KVMODE ? d * b1s[cb + 3] : 0.f);
            *(float4*)(out + (size_t)m * NLD + n0 + cb) = o;
        }
    }
}

// ---------------- edge pass 2: scores[e] = dot(Q[dst], K[mid]) / sqrt(C); track global max ----------------
__global__ void k_score(const void* __restrict__ ei2, int E2) {
    __shared__ float wm[8];
    int warp = (blockIdx.x * blockDim.x + threadIdx.x) >> 5;
    int lane = threadIdx.x & 31;
    int wid = threadIdx.x >> 5;
    float s = -3.4e38f;
    if (warp < E2) {
        int mid = ld_idx(ei2, warp);
        int dst = ld_idx(ei2, (size_t)E2 + warp);
        float4 q = *(const float4*)(g_Q + (size_t)dst * CDIM + lane * 4);
        float4 k = *(const float4*)(g_KV + (size_t)mid * 2 * CDIM + lane * 4);
        float d = q.x * k.x + q.y * k.y + q.z * k.z + q.w * k.w;
        #pragma unroll
        for (int o = 16; o > 0; o >>= 1) d += __shfl_xor_sync(0xffffffffu, d, o);
        s = d * 0.08838834764831845f;  // 1/sqrt(128)
        if (lane == 0) g_scores[warp] = s;
    }
    if (lane == 0) wm[wid] = s;
    __syncthreads();
    if (threadIdx.x == 0) {
        float m = wm[0];
        #pragma unroll
        for (int r = 1; r < 8; r++) m = fmaxf(m, wm[r]);
        atomicMax(&g_maxbits, flipf(m));
    }
}

// ---------------- global softmax: escore = exp(score - max), Z = sum ----------------
__global__ void k_expsum(int E2) {
    __shared__ float wm[8];
    float gm = unflipf(g_maxbits);
    float loc = 0.f;
    int i = blockIdx.x * blockDim.x + threadIdx.x;
    int stride = gridDim.x * blockDim.x;
    for (int t = i; t < E2; t += stride) {
        float es = __expf(g_scores[t] - gm);
        g_escore[t] = es;
        loc += es;
    }
    #pragma unroll
    for (int o = 16; o > 0; o >>= 1) loc += __shfl_xor_sync(0xffffffffu, loc, o);
    if ((threadIdx.x & 31) == 0) wm[threadIdx.x >> 5] = loc;
    __syncthreads();
    if (threadIdx.x == 0) {
        float bsum = 0.f;
        #pragma unroll
        for (int r = 0; r < 8; r++) bsum += wm[r];
        atomicAdd(&g_Z, bsum);
    }
}

// ---------------- edge pass 3: out[dst] += alpha_e * V[mid] ----------------
__global__ void k_scatter2(const void* __restrict__ ei2, float* __restrict__ out, int E2) {
    int warp = (blockIdx.x * blockDim.x + threadIdx.x) >> 5;
    int lane = threadIdx.x & 31;
    if (warp >= E2) return;
    int mid = ld_idx(ei2, warp);
    int dst = ld_idx(ei2, (size_t)E2 + warp);
    float w = g_escore[warp] * (1.0f / g_Z);
    float4 v = *(const float4*)(g_KV + (size_t)mid * 2 * CDIM + CDIM + lane * 4);
    float* p = out + (size_t)dst * CDIM + lane * 4;
    atomicAdd(p + 0, v.x * w);
    atomicAdd(p + 1, v.y * w);
    atomicAdd(p + 2, v.z * w);
    atomicAdd(p + 3, v.w * w);
}

// ---------------- launch ----------------
extern "C" void kernel_launch(void* const* d_in, const int* in_sizes, int n_in,
                              void* d_out, int out_size) {
    const float* x_src = (const float*)d_in[0];
    const float* x_mid = (const float*)d_in[1];
    const float* x_dst = (const float*)d_in[2];
    const void* ei1 = d_in[3];
    const void* ei2 = d_in[4];
    const float* W1w = (const float*)d_in[5];
    const float* W1b = (const float*)d_in[6];
    const float* W2w = (const float*)d_in[7];
    const float* W2b = (const float*)d_in[8];
    const float* qw  = (const float*)d_in[9];
    const float* qb  = (const float*)d_in[10];
    const float* kw  = (const float*)d_in[11];
    const float* kb  = (const float*)d_in[12];
    const float* vw  = (const float*)d_in[13];
    const float* vb  = (const float*)d_in[14];
    float* out = (float*)d_out;

    int E1 = in_sizes[3] / 2;
    int E2 = in_sizes[4] / 2;
    int Nmid = in_sizes[1] / CDIM;
    int Ndst = in_sizes[2] / CDIM;

    k_detect<<<1, 1>>>((const int*)ei1);
    k_zero<<<4096, 256>>>(out, out_size, Nmid);
    k_fold<<<(65536 + 16384 + 256 + 255) / 256, 256>>>(W1w, W2w, W1b, W2b, qw, kw, vw, kb, vb);
    k_scatter1<<<(E1 + 7) / 8, 256>>>(x_src, ei1, E1);

    dim3 gKV((Nmid + 127) / 128, 2);
    k_gemm<true><<<gKV, 256>>>(x_mid, nullptr, Nmid);
    dim3 gQ((Ndst + 127) / 128, 1);
    k_gemm<false><<<gQ, 256>>>(x_dst, qb, Ndst);

    k_score<<<(E2 + 7) / 8, 256>>>(ei2, E2);
    k_expsum<<<1024, 256>>>(E2);
    k_scatter2<<<(E2 + 7) / 8, 256>>>(ei2, out, E2);
}

// round 3
// speedup vs baseline: 1.3402x; 1.3402x over previous
#include <cuda_runtime.h>

#define CDIM 128
#define NMAX 50000
#define EMAX 640000

// ---------------- scratch (static device globals; no allocation) ----------------
__device__ __align__(16) float g_deg[NMAX];             // edge count per mid node
__device__ __align__(16) float g_s[NMAX * CDIM];        // scatter-sum of x_src per mid node
__device__ __align__(16) float g_KV[NMAX * 2 * CDIM];   // [m][0:128]=K, [m][128:256]=V
__device__ __align__(16) float g_Q[NMAX * CDIM];
__device__ __align__(16) float g_Wc[256 * 256];         // folded weights, input-major [i][j]
__device__ __align__(16) float g_WqT[CDIM * CDIM];      // q_w transposed, input-major
__device__ __align__(16) float g_bc0[256];              // {k_b, v_b}
__device__ __align__(16) float g_bc1[256];              // {k_w@(b1+b2), v_w@(b1+b2)}
__device__ __align__(16) float g_scores[EMAX];
__device__ __align__(16) float g_escore[EMAX];
__device__ unsigned g_maxbits;
__device__ float g_Z;
__device__ int g_idx64;   // 1 if edge indices are int64, 0 if int32

// adaptive index fetch: element e of a logical index array
__device__ __forceinline__ int ld_idx(const void* p, size_t e) {
    if (g_idx64) return (int)((const long long*)p)[e];
    return ((const int*)p)[e];
}

// vector reduction: one 16B red.global.add.v4.f32
__device__ __forceinline__ void red_add_v4(float* p, float4 v) {
    asm volatile("red.global.add.v4.f32 [%0], {%1, %2, %3, %4};"
                 :: "l"(p), "f"(v.x), "f"(v.y), "f"(v.z), "f"(v.w) : "memory");
}

// order-preserving float<->uint for atomicMax over signed floats
__device__ __forceinline__ unsigned flipf(float f) {
    unsigned u = __float_as_uint(f);
    return (u & 0x80000000u) ? ~u : (u | 0x80000000u);
}
__device__ __forceinline__ float unflipf(unsigned u) {
    return __uint_as_float((u & 0x80000000u) ? (u ^ 0x80000000u) : ~u);
}

// ---------------- detect index dtype (parallel) ----------------
// int64 indices < 2^31: every odd 32-bit word is 0. int32 random indices: not.
__global__ void k_detect(const int* __restrict__ ei1w) {
    int v = ei1w[2 * threadIdx.x + 1];
    unsigned any = __ballot_sync(0xffffffffu, v != 0);
    __shared__ int nz[16];
    if ((threadIdx.x & 31) == 0) nz[threadIdx.x >> 5] = (any != 0);
    __syncthreads();
    if (threadIdx.x == 0) {
        int a = 0;
        for (int r = 0; r < (int)(blockDim.x >> 5); r++) a |= nz[r];
        g_idx64 = !a;
    }
}

// ---------------- zero scratch + output ----------------
__global__ void k_zero(float* __restrict__ out, int n_out, int nmid) {
    int i = blockIdx.x * blockDim.x + threadIdx.x;
    int stride = gridDim.x * blockDim.x;
    float4 z = make_float4(0.f, 0.f, 0.f, 0.f);
    for (int t = i; t < nmid * CDIM / 4; t += stride) ((float4*)g_s)[t] = z;
    for (int t = i; t < n_out / 4; t += stride) ((float4*)out)[t] = z;
    for (int t = i; t < nmid; t += stride) g_deg[t] = 0.f;
    if (i == 0) { g_maxbits = 0u; g_Z = 0.f; }
}

// ---------------- fold weights: Wc = [[kw*W1, vw*W1],[kw*W2, vw*W2]] input-major ----------------
__global__ void k_fold(const float* __restrict__ W1w, const float* __restrict__ W2w,
                       const float* __restrict__ W1b, const float* __restrict__ W2b,
                       const float* __restrict__ qw,
                       const float* __restrict__ kw, const float* __restrict__ vw,
                       const float* __restrict__ kb, const float* __restrict__ vb) {
    int idx = blockIdx.x * blockDim.x + threadIdx.x;
    if (idx < 65536) {
        int i = idx >> 8, j = idx & 255;
        const float* Wa = (j < 128) ? kw : vw;
        int jj = j & 127;
        const float* Wx = (i < 128) ? W1w : W2w;
        int ii = i & 127;
        float acc = 0.f;
        #pragma unroll 8
        for (int t = 0; t < 128; t++) acc += Wa[jj * 128 + t] * Wx[t * 128 + ii];
        g_Wc[i * 256 + j] = acc;
    } else if (idx < 65536 + 16384) {
        int t2 = idx - 65536;
        int i = t2 >> 7, j = t2 & 127;
        g_WqT[i * 128 + j] = qw[j * 128 + i];
    } else if (idx < 65536 + 16384 + 256) {
        int j = idx - (65536 + 16384);
        const float* Wa = (j < 128) ? kw : vw;
        int jj = j & 127;
        float acc = 0.f;
        for (int t = 0; t < 128; t++) acc += Wa[jj * 128 + t] * (W1b[t] + W2b[t]);
        g_bc1[j] = acc;
        g_bc0[j] = (j < 128) ? kb[jj] : vb[jj];
    }
}

// ---------------- edge pass 1: deg[mid]++, s[mid] += x_src[src] ----------------
__global__ void k_scatter1(const float* __restrict__ xsrc, const void* __restrict__ ei1, int E1) {
    int warp = (blockIdx.x * blockDim.x + threadIdx.x) >> 5;
    int lane = threadIdx.x & 31;
    if (warp >= E1) return;
    int src = ld_idx(ei1, warp);
    int mid = ld_idx(ei1, (size_t)E1 + warp);
    float4 v = *(const float4*)(xsrc + (size_t)src * CDIM + lane * 4);
    red_add_v4(g_s + (size_t)mid * CDIM + lane * 4, v);
    if (lane == 0) atomicAdd(&g_deg[mid], 1.0f);
}

// ---------------- node GEMMs ----------------
// KVMODE=true : out[m][j] = sum_i X2[m][i]*Wc[i][j] + bc0[j] + deg[m]*bc1[j]
//               where X2 = [deg*x_mid | s], KDIM=256, NLD=256, out=g_KV
// KVMODE=false: out[m][j] = sum_i x_dst[m][i]*WqT[i][j] + q_b[j], KDIM=128, NLD=128, out=g_Q
template <bool KVMODE>
__global__ void __launch_bounds__(256) k_gemm(const float* __restrict__ X, const float* __restrict__ qb, int M) {
    const int KDIM = KVMODE ? 256 : 128;
    const int NLD  = KVMODE ? 256 : 128;
    float* out = KVMODE ? g_KV : g_Q;
    const float* W = KVMODE ? g_Wc : g_WqT;

    __shared__ __align__(16) float As[16][128];
    __shared__ __align__(16) float Bs[16][128];
    __shared__ __align__(16) float degS[128];
    __shared__ __align__(16) float b0s[128];
    __shared__ __align__(16) float b1s[128];

    int tid = threadIdx.x;
    int m0 = blockIdx.x * 128;
    int n0 = blockIdx.y * 128;

    if (tid < 128) {
        int m = m0 + tid;
        if (KVMODE) {
            degS[tid] = (m < M) ? g_deg[m] : 0.f;
            b0s[tid] = g_bc0[n0 + tid];
            b1s[tid] = g_bc1[n0 + tid];
        } else {
            b0s[tid] = qb[tid];
        }
    }
    __syncthreads();

    int ty = tid >> 4, tx = tid & 15;
    float acc[8][8];
    #pragma unroll
    for (int i = 0; i < 8; i++)
        #pragma unroll
        for (int j = 0; j < 8; j++) acc[i][j] = 0.f;

    for (int kt = 0; kt < KDIM / 16; kt++) {
        #pragma unroll
        for (int ld = 0; ld < 2; ld++) {
            int fid = tid + ld * 256;
            int r = fid >> 2;
            int kp = (fid & 3) * 4;
            int kg = kt * 16 + kp;
            int m = m0 + r;
            float4 av = make_float4(0.f, 0.f, 0.f, 0.f);
            if (m < M) {
                if (!KVMODE || kg < 128) {
                    av = *(const float4*)(X + (size_t)m * 128 + kg);
                    if (KVMODE) {
                        float d = degS[r];
                        av.x *= d; av.y *= d; av.z *= d; av.w *= d;
                    }
                } else {
                    av = *(const float4*)(g_s + (size_t)m * 128 + (kg - 128));
                }
            }
            As[kp + 0][r] = av.x;
            As[kp + 1][r] = av.y;
            As[kp + 2][r] = av.z;
            As[kp + 3][r] = av.w;
            int k = fid >> 5;
            int c4 = (fid & 31) * 4;
            *(float4*)&Bs[k][c4] = *(const float4*)(W + (size_t)(kt * 16 + k) * NLD + n0 + c4);
        }
        __syncthreads();
        #pragma unroll
        for (int kk = 0; kk < 16; kk++) {
            float a[8], b[8];
            *(float4*)(a)     = *(const float4*)&As[kk][ty * 8];
            *(float4*)(a + 4) = *(const float4*)&As[kk][ty * 8 + 4];
            *(float4*)(b)     = *(const float4*)&Bs[kk][tx * 8];
            *(float4*)(b + 4) = *(const float4*)&Bs[kk][tx * 8 + 4];
            #pragma unroll
            for (int i = 0; i < 8; i++)
                #pragma unroll
                for (int j = 0; j < 8; j++) acc[i][j] += a[i] * b[j];
        }
        __syncthreads();
    }

    #pragma unroll
    for (int i = 0; i < 8; i++) {
        int m = m0 + ty * 8 + i;
        if (m >= M) continue;
        float d = KVMODE ? degS[ty * 8 + i] : 0.f;
        #pragma unroll
        for (int j4 = 0; j4 < 8; j4 += 4) {
            int cb = tx * 8 + j4;
            float4 o;
            o.x = acc[i][j4 + 0] + b0s[cb + 0] + (KVMODE ? d * b1s[cb + 0] : 0.f);
            o.y = acc[i][j4 + 1] + b0s[cb + 1] + (KVMODE ? d * b1s[cb + 1] : 0.f);
            o.z = acc[i][j4 + 2] + b0s[cb + 2] + (KVMODE ? d * b1s[cb + 2] : 0.f);
            o.w = acc[i][j4 + 3] + b0s[cb + 3] + (KVMODE ? d * b1s[cb + 3] : 0.f);
            *(float4*)(out + (size_t)m * NLD + n0 + cb) = o;
        }
    }
}

// ---------------- edge pass 2: scores[e] = dot(Q[dst], K[mid]) / sqrt(C); track global max ----------------
__global__ void k_score(const void* __restrict__ ei2, int E2) {
    __shared__ float wm[8];
    int warp = (blockIdx.x * blockDim.x + threadIdx.x) >> 5;
    int lane = threadIdx.x & 31;
    int wid = threadIdx.x >> 5;
    float s = -3.4e38f;
    if (warp < E2) {
        int mid = ld_idx(ei2, warp);
        int dst = ld_idx(ei2, (size_t)E2 + warp);
        float4 q = *(const float4*)(g_Q + (size_t)dst * CDIM + lane * 4);
        float4 k = *(const float4*)(g_KV + (size_t)mid * 2 * CDIM + lane * 4);
        float d = q.x * k.x + q.y * k.y + q.z * k.z + q.w * k.w;
        #pragma unroll
        for (int o = 16; o > 0; o >>= 1) d += __shfl_xor_sync(0xffffffffu, d, o);
        s = d * 0.08838834764831845f;  // 1/sqrt(128)
        if (lane == 0) g_scores[warp] = s;
    }
    if (lane == 0) wm[wid] = s;
    __syncthreads();
    if (threadIdx.x == 0) {
        float m = wm[0];
        #pragma unroll
        for (int r = 1; r < 8; r++) m = fmaxf(m, wm[r]);
        atomicMax(&g_maxbits, flipf(m));
    }
}

// ---------------- global softmax: escore = exp(score - max), Z = sum ----------------
__global__ void k_expsum(int E2) {
    __shared__ float wm[8];
    float gm = unflipf(g_maxbits);
    float loc = 0.f;
    int i = blockIdx.x * blockDim.x + threadIdx.x;
    int stride = gridDim.x * blockDim.x;
    for (int t = i; t < E2 / 4; t += stride) {
        float4 sc = ((const float4*)g_scores)[t];
        float4 es;
        es.x = __expf(sc.x - gm);
        es.y = __expf(sc.y - gm);
        es.z = __expf(sc.z - gm);
        es.w = __expf(sc.w - gm);
        ((float4*)g_escore)[t] = es;
        loc += es.x + es.y + es.z + es.w;
    }
    for (int t = (E2 / 4) * 4 + i; t < E2; t += stride) {
        float es = __expf(g_scores[t] - gm);
        g_escore[t] = es;
        loc += es;
    }
    #pragma unroll
    for (int o = 16; o > 0; o >>= 1) loc += __shfl_xor_sync(0xffffffffu, loc, o);
    if ((threadIdx.x & 31) == 0) wm[threadIdx.x >> 5] = loc;
    __syncthreads();
    if (threadIdx.x == 0) {
        float bsum = 0.f;
        #pragma unroll
        for (int r = 0; r < 8; r++) bsum += wm[r];
        atomicAdd(&g_Z, bsum);
    }
}

// ---------------- edge pass 3: out[dst] += alpha_e * V[mid] ----------------
__global__ void k_scatter2(const void* __restrict__ ei2, float* __restrict__ out, int E2) {
    int warp = (blockIdx.x * blockDim.x + threadIdx.x) >> 5;
    int lane = threadIdx.x & 31;
    if (warp >= E2) return;
    int mid = ld_idx(ei2, warp);
    int dst = ld_idx(ei2, (size_t)E2 + warp);
    float w = g_escore[warp] * (1.0f / g_Z);
    float4 v = *(const float4*)(g_KV + (size_t)mid * 2 * CDIM + CDIM + lane * 4);
    v.x *= w; v.y *= w; v.z *= w; v.w *= w;
    red_add_v4(out + (size_t)dst * CDIM + lane * 4, v);
}

// ---------------- launch ----------------
extern "C" void kernel_launch(void* const* d_in, const int* in_sizes, int n_in,
                              void* d_out, int out_size) {
    const float* x_src = (const float*)d_in[0];
    const float* x_mid = (const float*)d_in[1];
    const float* x_dst = (const float*)d_in[2];
    const void* ei1 = d_in[3];
    const void* ei2 = d_in[4];
    const float* W1w = (const float*)d_in[5];
    const float* W1b = (const float*)d_in[6];
    const float* W2w = (const float*)d_in[7];
    const float* W2b = (const float*)d_in[8];
    const float* qw  = (const float*)d_in[9];
    const float* qb  = (const float*)d_in[10];
    const float* kw  = (const float*)d_in[11];
    const float* kb  = (const float*)d_in[12];
    const float* vw  = (const float*)d_in[13];
    const float* vb  = (const float*)d_in[14];
    float* out = (float*)d_out;

    int E1 = in_sizes[3] / 2;
    int E2 = in_sizes[4] / 2;
    int Nmid = in_sizes[1] / CDIM;
    int Ndst = in_sizes[2] / CDIM;

    k_detect<<<1, 512>>>((const int*)ei1);
    k_zero<<<2048, 256>>>(out, out_size, Nmid);
    k_fold<<<(65536 + 16384 + 256 + 255) / 256, 256>>>(W1w, W2w, W1b, W2b, qw, kw, vw, kb, vb);
    k_scatter1<<<(E1 + 7) / 8, 256>>>(x_src, ei1, E1);

    dim3 gKV((Nmid + 127) / 128, 2);
    k_gemm<true><<<gKV, 256>>>(x_mid, nullptr, Nmid);
    dim3 gQ((Ndst + 127) / 128, 1);
    k_gemm<false><<<gQ, 256>>>(x_dst, qb, Ndst);

    k_score<<<(E2 + 7) / 8, 256>>>(ei2, E2);
    k_expsum<<<1024, 256>>>(E2);
    k_scatter2<<<(E2 + 7) / 8, 256>>>(ei2, out, E2);
}

// round 4
// speedup vs baseline: 1.7754x; 1.3248x over previous
#include <cuda_runtime.h>
#include <cuda_bf16.h>

#define CDIM 128
#define NMAX 50000
#define EMAX 640000

// ---------------- scratch (static device globals; no allocation) ----------------
__device__ __align__(16) float g_deg[NMAX];             // edge count per mid node
__device__ __align__(16) float g_s[NMAX * CDIM];        // scatter-sum of x_src per mid node
__device__ __align__(16) float g_KV[NMAX * 2 * CDIM];   // [m][0:128]=K, [m][128:256]=V
__device__ __align__(16) float g_Q[NMAX * CDIM];
__device__ __align__(16) __nv_bfloat16 g_WcH[256 * 256]; // folded KV weights, [out n][in k], hi
__device__ __align__(16) __nv_bfloat16 g_WcL[256 * 256]; // lo
__device__ __align__(16) __nv_bfloat16 g_WqH[128 * 128]; // q weights [out n][in k], hi
__device__ __align__(16) __nv_bfloat16 g_WqL[128 * 128]; // lo
__device__ __align__(16) float g_bc0[256];              // {k_b, v_b}
__device__ __align__(16) float g_bc1[256];              // {k_w@(b1+b2), v_w@(b1+b2)}
__device__ __align__(16) float g_scores[EMAX];
__device__ __align__(16) float g_escore[EMAX];
__device__ unsigned g_maxbits;
__device__ float g_Z;
__device__ int g_idx64;   // 1 if edge indices are int64, 0 if int32

// adaptive index fetch
__device__ __forceinline__ int ld_idx(const void* p, size_t e) {
    if (g_idx64) return (int)((const long long*)p)[e];
    return ((const int*)p)[e];
}

// vector reduction: one 16B red.global.add.v4.f32
__device__ __forceinline__ void red_add_v4(float* p, float4 v) {
    asm volatile("red.global.add.v4.f32 [%0], {%1, %2, %3, %4};"
                 :: "l"(p), "f"(v.x), "f"(v.y), "f"(v.z), "f"(v.w) : "memory");
}

__device__ __forceinline__ unsigned flipf(float f) {
    unsigned u = __float_as_uint(f);
    return (u & 0x80000000u) ? ~u : (u | 0x80000000u);
}
__device__ __forceinline__ float unflipf(unsigned u) {
    return __uint_as_float((u & 0x80000000u) ? (u ^ 0x80000000u) : ~u);
}

__device__ __forceinline__ unsigned pack_bf2(float x, float y) {
    __nv_bfloat162 h = __floats2bfloat162_rn(x, y);
    return *(unsigned*)&h;
}

// ---------------- detect index dtype (parallel) ----------------
__global__ void k_detect(const int* __restrict__ ei1w) {
    int v = ei1w[2 * threadIdx.x + 1];
    unsigned any = __ballot_sync(0xffffffffu, v != 0);
    __shared__ int nz[16];
    if ((threadIdx.x & 31) == 0) nz[threadIdx.x >> 5] = (any != 0);
    __syncthreads();
    if (threadIdx.x == 0) {
        int a = 0;
        for (int r = 0; r < (int)(blockDim.x >> 5); r++) a |= nz[r];
        g_idx64 = !a;
    }
}

// ---------------- zero scratch + output ----------------
__global__ void k_zero(float* __restrict__ out, int n_out, int nmid) {
    int i = blockIdx.x * blockDim.x + threadIdx.x;
    int stride = gridDim.x * blockDim.x;
    float4 z = make_float4(0.f, 0.f, 0.f, 0.f);
    for (int t = i; t < nmid * CDIM / 4; t += stride) ((float4*)g_s)[t] = z;
    for (int t = i; t < n_out / 4; t += stride) ((float4*)out)[t] = z;
    for (int t = i; t < nmid; t += stride) g_deg[t] = 0.f;
    if (i == 0) { g_maxbits = 0u; g_Z = 0.f; }
}

// ---------------- fold weights ----------------
// KV B[n][k]: n in {K-out, V-out} (256), k in {x_mid-in, s-in} (256):
//   B[j][i] = Wc[i][j] = sum_t Wa[j%128][t] * Wx[t][i%128],  Wa = kw|vw, Wx = W1|W2
// Q  B[n][k] = qw[n*128+k] (no transpose needed)
__global__ void k_fold(const float* __restrict__ W1w, const float* __restrict__ W2w,
                       const float* __restrict__ W1b, const float* __restrict__ W2b,
                       const float* __restrict__ qw,
                       const float* __restrict__ kw, const float* __restrict__ vw,
                       const float* __restrict__ kb, const float* __restrict__ vb) {
    int idx = blockIdx.x * blockDim.x + threadIdx.x;
    if (idx < 65536) {
        int i = idx >> 8, j = idx & 255;
        const float* Wa = (j < 128) ? kw : vw;
        int jj = j & 127;
        const float* Wx = (i < 128) ? W1w : W2w;
        int ii = i & 127;
        float acc = 0.f;
        #pragma unroll 8
        for (int t = 0; t < 128; t++) acc += Wa[jj * 128 + t] * Wx[t * 128 + ii];
        __nv_bfloat16 h = __float2bfloat16(acc);
        g_WcH[j * 256 + i] = h;
        g_WcL[j * 256 + i] = __float2bfloat16(acc - __bfloat162float(h));
    } else if (idx < 65536 + 16384) {
        int t2 = idx - 65536;
        float a = qw[t2];
        __nv_bfloat16 h = __float2bfloat16(a);
        g_WqH[t2] = h;
        g_WqL[t2] = __float2bfloat16(a - __bfloat162float(h));
    } else if (idx < 65536 + 16384 + 256) {
        int j = idx - (65536 + 16384);
        const float* Wa = (j < 128) ? kw : vw;
        int jj = j & 127;
        float acc = 0.f;
        for (int t = 0; t < 128; t++) acc += Wa[jj * 128 + t] * (W1b[t] + W2b[t]);
        g_bc1[j] = acc;
        g_bc0[j] = (j < 128) ? kb[jj] : vb[jj];
    }
}

// ---------------- edge pass 1 ----------------
__global__ void k_scatter1(const float* __restrict__ xsrc, const void* __restrict__ ei1, int E1) {
    int warp = (blockIdx.x * blockDim.x + threadIdx.x) >> 5;
    int lane = threadIdx.x & 31;
    if (warp >= E1) return;
    int src = ld_idx(ei1, warp);
    int mid = ld_idx(ei1, (size_t)E1 + warp);
    float4 v = *(const float4*)(xsrc + (size_t)src * CDIM + lane * 4);
    red_add_v4(g_s + (size_t)mid * CDIM + lane * 4, v);
    if (lane == 0) atomicAdd(&g_deg[mid], 1.0f);
}

// ---------------- tensor-core node GEMMs (bf16 3-term split) ----------------
// KVMODE=true : out[m][n0+j] = sum_i X2[m][i]*B[n0+j][i] + bc0 + deg*bc1, X2=[deg*x_mid | s], K=256
// KVMODE=false: out[m][j] = sum_i x_dst[m][i]*qw[j][i] + q_b[j], K=128
#define ASTR 24   // smem row stride in halves (48B): conflict-free frag loads
template <bool KVMODE>
__global__ void __launch_bounds__(256, 2) k_gemm_tc(const float* __restrict__ X,
                                                    const float* __restrict__ qb, int M) {
    const int KDIM = KVMODE ? 256 : 128;
    const int NLD  = KVMODE ? 256 : 128;
    float* out = KVMODE ? g_KV : g_Q;
    const __nv_bfloat16* BHg = KVMODE ? g_WcH : g_WqH;
    const __nv_bfloat16* BLg = KVMODE ? g_WcL : g_WqL;

    __shared__ __align__(16) unsigned short Ah[128 * ASTR];
    __shared__ __align__(16) unsigned short Al[128 * ASTR];
    __shared__ __align__(16) unsigned short Bh[128 * ASTR];
    __shared__ __align__(16) unsigned short Bl[128 * ASTR];
    __shared__ float degS[128], b0s[128], b1s[128];

    int tid = threadIdx.x;
    int m0 = blockIdx.x * 128, n0 = blockIdx.y * 128;

    if (tid < 128) {
        int m = m0 + tid;
        if (KVMODE) {
            degS[tid] = (m < M) ? g_deg[m] : 0.f;
            b0s[tid] = g_bc0[n0 + tid];
            b1s[tid] = g_bc1[n0 + tid];
        } else {
            b0s[tid] = qb[tid];
        }
    }
    __syncthreads();

    int lane = tid & 31, wid = tid >> 5;
    int g = lane >> 2, t = lane & 3;
    int wm = (wid >> 2) * 64, wn = (wid & 3) * 32;

    float acc[4][4][4];
    #pragma unroll
    for (int mt = 0; mt < 4; mt++)
        #pragma unroll
        for (int nt = 0; nt < 4; nt++)
            #pragma unroll
            for (int r = 0; r < 4; r++) acc[mt][nt][r] = 0.f;

    int m_r = tid >> 1;            // 0..127: tile row (A) / tile n-row (B)
    int khalf = (tid & 1) * 8;     // 0 or 8

    for (int kt = 0; kt < KDIM / 16; kt++) {
        int kg = kt * 16 + khalf;
        // ---- A tile: load 8 fp32, split hi/lo bf16 ----
        float f[8];
        {
            int m = m0 + m_r;
            if (m < M) {
                const float* src;
                float d = 1.f;
                if (!KVMODE) {
                    src = X + (size_t)m * 128 + kg;
                } else if (kg < 128) {
                    src = X + (size_t)m * 128 + kg;
                    d = degS[m_r];
                } else {
                    src = g_s + (size_t)m * 128 + (kg - 128);
                }
                float4 v0 = *(const float4*)src;
                float4 v1 = *(const float4*)(src + 4);
                f[0] = v0.x * d; f[1] = v0.y * d; f[2] = v0.z * d; f[3] = v0.w * d;
                f[4] = v1.x * d; f[5] = v1.y * d; f[6] = v1.z * d; f[7] = v1.w * d;
            } else {
                #pragma unroll
                for (int j = 0; j < 8; j++) f[j] = 0.f;
            }
        }
        unsigned hi[4], lo[4];
        #pragma unroll
        for (int j = 0; j < 4; j++) {
            __nv_bfloat162 h2 = __floats2bfloat162_rn(f[2 * j], f[2 * j + 1]);
            hi[j] = *(unsigned*)&h2;
            float r0 = f[2 * j]     - __bfloat162float(h2.x);
            float r1 = f[2 * j + 1] - __bfloat162float(h2.y);
            lo[j] = pack_bf2(r0, r1);
        }
        *(uint4*)&Ah[m_r * ASTR + khalf] = make_uint4(hi[0], hi[1], hi[2], hi[3]);
        *(uint4*)&Al[m_r * ASTR + khalf] = make_uint4(lo[0], lo[1], lo[2], lo[3]);
        // ---- B tile: direct bf16 copy ----
        size_t boff = (size_t)(n0 + m_r) * KDIM + kg;
        *(uint4*)&Bh[m_r * ASTR + khalf] = *(const uint4*)(BHg + boff);
        *(uint4*)&Bl[m_r * ASTR + khalf] = *(const uint4*)(BLg + boff);
        __syncthreads();

        // ---- 3 precision terms: AhBh, AhBl, AlBh ----
        #pragma unroll
        for (int term = 0; term < 3; term++) {
            const unsigned short* As = (term == 2) ? Al : Ah;
            const unsigned short* Bs = (term == 1) ? Bl : Bh;
            unsigned b[4][2];
            #pragma unroll
            for (int nt = 0; nt < 4; nt++) {
                int nb = (wn + nt * 8 + g) * ASTR + 2 * t;
                b[nt][0] = *(const unsigned*)&Bs[nb];
                b[nt][1] = *(const unsigned*)&Bs[nb + 8];
            }
            #pragma unroll
            for (int mt = 0; mt < 4; mt++) {
                int ra = (wm + mt * 16 + g) * ASTR + 2 * t;
                unsigned a0 = *(const unsigned*)&As[ra];
                unsigned a1 = *(const unsigned*)&As[ra + 8 * ASTR];
                unsigned a2 = *(const unsigned*)&As[ra + 8];
                unsigned a3 = *(const unsigned*)&As[ra + 8 * ASTR + 8];
                #pragma unroll
                for (int nt = 0; nt < 4; nt++) {
                    asm volatile(
                        "mma.sync.aligned.m16n8k16.row.col.f32.bf16.bf16.f32 "
                        "{%0,%1,%2,%3}, {%4,%5,%6,%7}, {%8,%9}, {%0,%1,%2,%3};"
                        : "+f"(acc[mt][nt][0]), "+f"(acc[mt][nt][1]),
                          "+f"(acc[mt][nt][2]), "+f"(acc[mt][nt][3])
                        : "r"(a0), "r"(a1), "r"(a2), "r"(a3),
                          "r"(b[nt][0]), "r"(b[nt][1]));
                }
            }
        }
        __syncthreads();
    }

    // ---- epilogue: bias (+ deg*bias1 for KV) ----
    #pragma unroll
    for (int mt = 0; mt < 4; mt++) {
        int r0l = wm + mt * 16 + g;
        int r1l = r0l + 8;
        int mA = m0 + r0l, mB = m0 + r1l;
        float dA = KVMODE ? degS[r0l] : 0.f;
        float dB = KVMODE ? degS[r1l] : 0.f;
        #pragma unroll
        for (int nt = 0; nt < 4; nt++) {
            int cl = wn + nt * 8 + 2 * t;
            float bia0 = b0s[cl]     + (KVMODE ? dA * b1s[cl]     : 0.f);
            float bia1 = b0s[cl + 1] + (KVMODE ? dA * b1s[cl + 1] : 0.f);
            float bib0 = b0s[cl]     + (KVMODE ? dB * b1s[cl]     : 0.f);
            float bib1 = b0s[cl + 1] + (KVMODE ? dB * b1s[cl + 1] : 0.f);
            if (mA < M) {
                float2 o = make_float2(acc[mt][nt][0] + bia0, acc[mt][nt][1] + bia1);
                *(float2*)(out + (size_t)mA * NLD + n0 + cl) = o;
            }
            if (mB < M) {
                float2 o = make_float2(acc[mt][nt][2] + bib0, acc[mt][nt][3] + bib1);
                *(float2*)(out + (size_t)mB * NLD + n0 + cl) = o;
            }
        }
    }
}

// ---------------- edge pass 2: scores + global max ----------------
__global__ void k_score(const void* __restrict__ ei2, int E2) {
    __shared__ float wm[8];
    int warp = (blockIdx.x * blockDim.x + threadIdx.x) >> 5;
    int lane = threadIdx.x & 31;
    int wid = threadIdx.x >> 5;
    float s = -3.4e38f;
    if (warp < E2) {
        int mid = ld_idx(ei2, warp);
        int dst = ld_idx(ei2, (size_t)E2 + warp);
        float4 q = *(const float4*)(g_Q + (size_t)dst * CDIM + lane * 4);
        float4 k = *(const float4*)(g_KV + (size_t)mid * 2 * CDIM + lane * 4);
        float d = q.x * k.x + q.y * k.y + q.z * k.z + q.w * k.w;
        #pragma unroll
        for (int o = 16; o > 0; o >>= 1) d += __shfl_xor_sync(0xffffffffu, d, o);
        s = d * 0.08838834764831845f;  // 1/sqrt(128)
        if (lane == 0) g_scores[warp] = s;
    }
    if (lane == 0) wm[wid] = s;
    __syncthreads();
    if (threadIdx.x == 0) {
        float m = wm[0];
        #pragma unroll
        for (int r = 1; r < 8; r++) m = fmaxf(m, wm[r]);
        atomicMax(&g_maxbits, flipf(m));
    }
}

// ---------------- global softmax: escore = exp(score - max), Z = sum ----------------
__global__ void k_expsum(int E2) {
    __shared__ float wm[8];
    float gm = unflipf(g_maxbits);
    float loc = 0.f;
    int i = blockIdx.x * blockDim.x + threadIdx.x;
    int stride = gridDim.x * blockDim.x;
    for (int t = i; t < E2 / 4; t += stride) {
        float4 sc = ((const float4*)g_scores)[t];
        float4 es;
        es.x = __expf(sc.x - gm);
        es.y = __expf(sc.y - gm);
        es.z = __expf(sc.z - gm);
        es.w = __expf(sc.w - gm);
        ((float4*)g_escore)[t] = es;
        loc += es.x + es.y + es.z + es.w;
    }
    for (int t = (E2 / 4) * 4 + i; t < E2; t += stride) {
        float es = __expf(g_scores[t] - gm);
        g_escore[t] = es;
        loc += es;
    }
    #pragma unroll
    for (int o = 16; o > 0; o >>= 1) loc += __shfl_xor_sync(0xffffffffu, loc, o);
    if ((threadIdx.x & 31) == 0) wm[threadIdx.x >> 5] = loc;
    __syncthreads();
    if (threadIdx.x == 0) {
        float bsum = 0.f;
        #pragma unroll
        for (int r = 0; r < 8; r++) bsum += wm[r];
        atomicAdd(&g_Z, bsum);
    }
}

// ---------------- edge pass 3: out[dst] += alpha_e * V[mid] ----------------
__global__ void k_scatter2(const void* __restrict__ ei2, float* __restrict__ out, int E2) {
    int warp = (blockIdx.x * blockDim.x + threadIdx.x) >> 5;
    int lane = threadIdx.x & 31;
    if (warp >= E2) return;
    int mid = ld_idx(ei2, warp);
    int dst = ld_idx(ei2, (size_t)E2 + warp);
    float w = g_escore[warp] * (1.0f / g_Z);
    float4 v = *(const float4*)(g_KV + (size_t)mid * 2 * CDIM + CDIM + lane * 4);
    v.x *= w; v.y *= w; v.z *= w; v.w *= w;
    red_add_v4(out + (size_t)dst * CDIM + lane * 4, v);
}

// ---------------- launch ----------------
extern "C" void kernel_launch(void* const* d_in, const int* in_sizes, int n_in,
                              void* d_out, int out_size) {
    const float* x_src = (const float*)d_in[0];
    const float* x_mid = (const float*)d_in[1];
    const float* x_dst = (const float*)d_in[2];
    const void* ei1 = d_in[3];
    const void* ei2 = d_in[4];
    const float* W1w = (const float*)d_in[5];
    const float* W1b = (const float*)d_in[6];
    const float* W2w = (const float*)d_in[7];
    const float* W2b = (const float*)d_in[8];
    const float* qw  = (const float*)d_in[9];
    const float* qb  = (const float*)d_in[10];
    const float* kw  = (const float*)d_in[11];
    const float* kb  = (const float*)d_in[12];
    const float* vw  = (const float*)d_in[13];
    const float* vb  = (const float*)d_in[14];
    float* out = (float*)d_out;

    int E1 = in_sizes[3] / 2;
    int E2 = in_sizes[4] / 2;
    int Nmid = in_sizes[1] / CDIM;
    int Ndst = in_sizes[2] / CDIM;

    k_detect<<<1, 512>>>((const int*)ei1);
    k_zero<<<2048, 256>>>(out, out_size, Nmid);
    k_fold<<<(65536 + 16384 + 256 + 255) / 256, 256>>>(W1w, W2w, W1b, W2b, qw, kw, vw, kb, vb);
    k_scatter1<<<(E1 + 7) / 8, 256>>>(x_src, ei1, E1);

    dim3 gKV((Nmid + 127) / 128, 2);
    k_gemm_tc<true><<<gKV, 256>>>(x_mid, nullptr, Nmid);
    dim3 gQ((Ndst + 127) / 128, 1);
    k_gemm_tc<false><<<gQ, 256>>>(x_dst, qb, Ndst);

    k_score<<<(E2 + 7) / 8, 256>>>(ei2, E2);
    k_expsum<<<1024, 256>>>(E2);
    k_scatter2<<<(E2 + 7) / 8, 256>>>(ei2, out, E2);
}